// round 6
// baseline (speedup 1.0000x reference)
#include <cuda_runtime.h>
#include <cuda_bf16.h>

// FM layer: out[b,:] = 0.5 * ((sum v*e)^2 - sum (v*e)^2), batch_ids sorted.
// Inputs:
//   d_in[0] feature_embedding float32 [1e6, 64]
//   d_in[1] feature_vals      float32 [819200]
//   d_in[2] batch_ids         int32   [819200] sorted
//   d_in[3] feat_ids          int32   [819200]
//   d_in[4] batch_size        int32   [1]
// Output float32 [4096, 64]

#define EMBED   64
#define GROUPS  8             // 8 warps per CTA
#define BLOCK   256
#define MAXB    4096

__device__ int    g_starts[MAXB + 1];
__device__ float2 g_ps[2][MAXB][32];   // partial S per half  (4096*32 float2 * 2)
__device__ float2 g_pq[2][MAXB][32];   // partial Q per half

// Sorted batch_ids -> CSR row starts. 4 elems/thread, exactly-once, no atomics.
__global__ void boundary_kernel(const int* __restrict__ bids, int nnz, int batch)
{
    int base = 4 * (blockIdx.x * blockDim.x + threadIdx.x);
    if (base > nnz) return;
    int prev = (base == 0) ? -1 : __ldg(bids + base - 1);
    if (base + 3 < nnz) {
        int4 c = __ldcs((const int4*)(bids + base));
        int cs[4] = {c.x, c.y, c.z, c.w};
        #pragma unroll
        for (int k = 0; k < 4; k++) {
            for (int b = prev + 1; b <= cs[k]; b++) g_starts[b] = base + k;
            prev = cs[k];
        }
    } else {
        #pragma unroll
        for (int k = 0; k < 4; k++) {
            int p = base + k;
            if (p > nnz) break;
            int cur = (p == nnz) ? batch : __ldg(bids + p);
            for (int b = prev + 1; b <= cur; b++) g_starts[b] = p;
            prev = cur;
        }
    }
}

__device__ __forceinline__ void fm_acc2(float v, float2 e,
                                        float& sx, float& sy, float& qx, float& qy)
{
    float ax = v * e.x, ay = v * e.y;
    sx += ax; qx = fmaf(ax, ax, qx);
    sy += ay; qy = fmaf(ay, ay, qy);
}

// One CTA = one HALF of a batch segment. Writes partial (S,Q) to scratch.
__global__ __launch_bounds__(BLOCK, 8)
void fm_half(const float* __restrict__ emb,
             const float* __restrict__ vals,
             const int*   __restrict__ fids)
{
    const int c    = blockIdx.x;
    const int b    = c >> 1;
    const int half = c & 1;
    const int t = threadIdx.x & 31;     // float2 lane: dims [2t, 2t+1]
    const int g = threadIdx.x >> 5;     // warp/group 0..7

    const int lo0 = g_starts[b];
    const int hi0 = g_starts[b + 1];
    const int mid = (lo0 + hi0) >> 1;
    const int lo  = half ? mid : lo0;
    const int hi  = half ? hi0 : mid;

    const float2* __restrict__ emb2 = (const float2*)emb;

    float sx = 0.f, sy = 0.f, qx = 0.f, qy = 0.f;

    int lo4 = (lo + 3) & ~3;
    int hi4 = hi & ~3;

    if (lo4 > hi4) {
        // tiny half (< 8 elems): one scalar element per group
        int idx = lo + g;
        if (idx < hi) {
            int   f = __ldg(fids + idx);
            float v = __ldg(vals + idx);
            float2 e = __ldg(emb2 + f * 32 + t);
            fm_acc2(v, e, sx, sy, qx, qy);
        }
    } else {
        // scalar head [lo, lo4): <=3 elems, one per group
        {
            int idx = lo + g;
            if (idx < lo4) {
                int   f = __ldg(fids + idx);
                float v = __ldg(vals + idx);
                float2 e = __ldg(emb2 + f * 32 + t);
                fm_acc2(v, e, sx, sy, qx, qy);
            }
        }
        // scalar tail [hi4, hi): <=3 elems
        {
            int idx = hi4 + g;
            if (idx < hi) {
                int   f = __ldg(fids + idx);
                float v = __ldg(vals + idx);
                float2 e = __ldg(emb2 + f * 32 + t);
                fm_acc2(v, e, sx, sy, qx, qy);
            }
        }
        // aligned quad region: streams evict-first, embedding rows via L2
        int nb = (hi4 - lo4) >> 2;
        for (int j = g; j < nb; j += GROUPS) {
            const int pos = lo4 + 4 * j;
            int4   f = __ldcs((const int4*)  (fids + pos));
            float4 v = __ldcs((const float4*)(vals + pos));
            float2 e0 = __ldg(emb2 + f.x * 32 + t);
            float2 e1 = __ldg(emb2 + f.y * 32 + t);
            float2 e2 = __ldg(emb2 + f.z * 32 + t);
            float2 e3 = __ldg(emb2 + f.w * 32 + t);
            fm_acc2(v.x, e0, sx, sy, qx, qy);
            fm_acc2(v.y, e1, sx, sy, qx, qy);
            fm_acc2(v.z, e2, sx, sy, qx, qy);
            fm_acc2(v.w, e3, sx, sy, qx, qy);
        }
    }

    // combine 8 groups through shared memory, then write CTA partials
    __shared__ float2 sh_s[GROUPS][32];
    __shared__ float2 sh_q[GROUPS][32];
    sh_s[g][t] = make_float2(sx, sy);
    sh_q[g][t] = make_float2(qx, qy);
    __syncthreads();

    if (g == 0) {
        float Sx = sx, Sy = sy, Qx = qx, Qy = qy;
        #pragma unroll
        for (int k = 1; k < GROUPS; k++) {
            float2 a = sh_s[k][t], cc = sh_q[k][t];
            Sx += a.x; Sy += a.y;
            Qx += cc.x; Qy += cc.y;
        }
        g_ps[half][b][t] = make_float2(Sx, Sy);
        g_pq[half][b][t] = make_float2(Qx, Qy);
    }
}

// Final combine: out[b,:] = 0.5 * ((S0+S1)^2 - (Q0+Q1))
__global__ void fm_combine(float* __restrict__ out, int total)  // total = batch*32
{
    int idx = blockIdx.x * blockDim.x + threadIdx.x;
    if (idx >= total) return;
    int b = idx >> 5, t = idx & 31;
    float2 s0 = g_ps[0][b][t], s1 = g_ps[1][b][t];
    float2 q0 = g_pq[0][b][t], q1 = g_pq[1][b][t];
    float Sx = s0.x + s1.x, Sy = s0.y + s1.y;
    float Qx = q0.x + q1.x, Qy = q0.y + q1.y;
    float2 o;
    o.x = 0.5f * (Sx * Sx - Qx);
    o.y = 0.5f * (Sy * Sy - Qy);
    ((float2*)out)[idx] = o;
}

extern "C" void kernel_launch(void* const* d_in, const int* in_sizes, int n_in,
                              void* d_out, int out_size)
{
    const float* emb  = (const float*)d_in[0];
    const float* vals = (const float*)d_in[1];
    const int*   bids = (const int*)d_in[2];
    const int*   fids = (const int*)d_in[3];
    float* out = (float*)d_out;

    int nnz   = in_sizes[1];
    int batch = out_size / EMBED;   // 4096

    int bthreads = nnz / 4 + 1;
    boundary_kernel<<<(bthreads + 255) / 256, 256>>>(bids, nnz, batch);
    fm_half<<<2 * batch, BLOCK>>>(emb, vals, fids);
    int total = batch * 32;
    fm_combine<<<(total + 255) / 256, 256>>>(out, total);
}

// round 7
// speedup vs baseline: 1.0520x; 1.0520x over previous
#include <cuda_runtime.h>
#include <cuda_bf16.h>

// FM layer: out[b,:] = 0.5 * ((sum v*e)^2 - sum (v*e)^2), batch_ids sorted.
// Single fused kernel: warp 0 finds the CTA's segment bounds with a
// half-warp-parallel lower_bound (5 dependent probes instead of ~20),
// then all 8 warps run the proven 4-deep gather pipeline.
//
// Inputs:
//   d_in[0] feature_embedding float32 [1e6, 64]
//   d_in[1] feature_vals      float32 [819200]
//   d_in[2] batch_ids         int32   [819200] sorted
//   d_in[3] feat_ids          int32   [819200]
//   d_in[4] batch_size        int32   [1]
// Output float32 [4096, 64]

#define EMBED  64
#define GROUPS 8              // 8 warps per CTA, group-strided over the segment
#define BLOCK  256

__global__ __launch_bounds__(BLOCK, 8)
void fm_fused(const float* __restrict__ emb,
              const float* __restrict__ vals,
              const int*   __restrict__ bids,
              const int*   __restrict__ fids,
              float*       __restrict__ out,
              int nnz)
{
    const int b = blockIdx.x;
    const int t = threadIdx.x & 31;     // float2 lane: dims [2t, 2t+1]
    const int g = threadIdx.x >> 5;     // warp/group 0..7

    __shared__ int sbounds[2];          // [0] = lower_bound(b), [1] = lower_bound(b+1)

    if (g == 0) {
        // Half-warp-parallel lower_bound: lanes 0-15 search x=b, 16-31 x=b+1.
        const int      half = t >> 4;
        const int      lh   = t & 15;
        const int      x    = b + half;
        const unsigned hmask = 0xFFFFu << (half * 16);

        int lo = 0, hi = nnz;
        // invariant: answer in [lo, hi]
        while (hi - lo > 16) {
            int chunk = ((hi - lo) + 15) >> 4;
            int p = lo + lh * chunk;
            bool lt = (p < hi) && (__ldg(bids + p) < x);
            unsigned m = (__ballot_sync(hmask, lt) >> (half * 16)) & 0xFFFFu;
            int c = __popc(m);              // contiguous low-bit run (sorted)
            if (c == 0) { hi = lo; break; } // bids[lo] >= x -> answer == lo
            int nhi = (c < 16) ? min(lo + c * chunk, hi) : hi;
            lo = lo + (c - 1) * chunk + 1;
            hi = nhi;
        }
        {   // final: count elements < x in [lo, hi)
            int p = lo + lh;
            bool lt = (p < hi) && (__ldg(bids + p) < x);
            unsigned m = (__ballot_sync(hmask, lt) >> (half * 16)) & 0xFFFFu;
            lo += __popc(m);
        }
        if (lh == 0) sbounds[half] = lo;
    }
    __syncthreads();

    const int lo = sbounds[0];
    const int hi = sbounds[1];

    const float2* __restrict__ emb2 = (const float2*)emb;

    float sx = 0.f, sy = 0.f, qx = 0.f, qy = 0.f;

    int i = lo + g;
    // 4-deep gather pipeline per thread (R2 body, best measured: 38.0us)
    for (; i + 3 * GROUPS < hi; i += 4 * GROUPS) {
        int f0 = __ldg(fids + i);
        int f1 = __ldg(fids + i +     GROUPS);
        int f2 = __ldg(fids + i + 2 * GROUPS);
        int f3 = __ldg(fids + i + 3 * GROUPS);
        float v0 = __ldg(vals + i);
        float v1 = __ldg(vals + i +     GROUPS);
        float v2 = __ldg(vals + i + 2 * GROUPS);
        float v3 = __ldg(vals + i + 3 * GROUPS);
        float2 e0 = __ldg(emb2 + f0 * 32 + t);
        float2 e1 = __ldg(emb2 + f1 * 32 + t);
        float2 e2 = __ldg(emb2 + f2 * 32 + t);
        float2 e3 = __ldg(emb2 + f3 * 32 + t);

        float ax, ay;
        ax = v0 * e0.x; ay = v0 * e0.y; sx += ax; qx = fmaf(ax, ax, qx); sy += ay; qy = fmaf(ay, ay, qy);
        ax = v1 * e1.x; ay = v1 * e1.y; sx += ax; qx = fmaf(ax, ax, qx); sy += ay; qy = fmaf(ay, ay, qy);
        ax = v2 * e2.x; ay = v2 * e2.y; sx += ax; qx = fmaf(ax, ax, qx); sy += ay; qy = fmaf(ay, ay, qy);
        ax = v3 * e3.x; ay = v3 * e3.y; sx += ax; qx = fmaf(ax, ax, qx); sy += ay; qy = fmaf(ay, ay, qy);
    }
    for (; i < hi; i += GROUPS) {
        int   f = __ldg(fids + i);
        float v = __ldg(vals + i);
        float2 e = __ldg(emb2 + f * 32 + t);
        float ax = v * e.x, ay = v * e.y;
        sx += ax; qx = fmaf(ax, ax, qx);
        sy += ay; qy = fmaf(ay, ay, qy);
    }

    // combine 8 groups through shared memory
    __shared__ float ssx[GROUPS][32], ssy[GROUPS][32];
    __shared__ float sqx[GROUPS][32], sqy[GROUPS][32];
    ssx[g][t] = sx; ssy[g][t] = sy;
    sqx[g][t] = qx; sqy[g][t] = qy;
    __syncthreads();

    if (g == 0) {
        float Sx = sx, Sy = sy, Qx = qx, Qy = qy;
        #pragma unroll
        for (int k = 1; k < GROUPS; k++) {
            Sx += ssx[k][t]; Sy += ssy[k][t];
            Qx += sqx[k][t]; Qy += sqy[k][t];
        }
        float2 o;
        o.x = 0.5f * (Sx * Sx - Qx);
        o.y = 0.5f * (Sy * Sy - Qy);
        ((float2*)out)[b * 32 + t] = o;
    }
}

extern "C" void kernel_launch(void* const* d_in, const int* in_sizes, int n_in,
                              void* d_out, int out_size)
{
    const float* emb  = (const float*)d_in[0];
    const float* vals = (const float*)d_in[1];
    const int*   bids = (const int*)d_in[2];
    const int*   fids = (const int*)d_in[3];
    float* out = (float*)d_out;

    int nnz   = in_sizes[1];
    int batch = out_size / EMBED;   // 4096

    fm_fused<<<batch, BLOCK>>>(emb, vals, bids, fids, out, nnz);
}

// round 8
// speedup vs baseline: 1.1543x; 1.0972x over previous
#include <cuda_runtime.h>
#include <cuda_bf16.h>

// FM layer: out[b,:] = 0.5 * ((sum v*e)^2 - sum (v*e)^2), batch_ids sorted.
// Two kernels:
//   1) boundary_kernel: sorted batch_ids -> CSR row starts, 16 elems/thread
//      (4x int4 loads in flight -> latency covered), exactly-once, no atomics.
//   2) fm_main: proven R2 gather body (measured 38.0us standalone).
//
// Inputs:
//   d_in[0] feature_embedding float32 [1e6, 64]
//   d_in[1] feature_vals      float32 [819200]
//   d_in[2] batch_ids         int32   [819200] sorted
//   d_in[3] feat_ids          int32   [819200]
//   d_in[4] batch_size        int32   [1]
// Output float32 [4096, 64]

#define EMBED  64
#define GROUPS 8              // 8 warps per CTA, group-strided over the segment
#define BLOCK  256
#define EPT    16             // boundary kernel: elements per thread

__device__ int g_starts[4097];

__global__ void boundary_kernel(const int* __restrict__ bids, int nnz, int batch)
{
    int base = EPT * (blockIdx.x * blockDim.x + threadIdx.x);
    if (base >= nnz) {
        // one extra thread-slot handles nothing; final fill handled by owner of array end
        return;
    }

    int prev = (base == 0) ? -1 : __ldg(bids + base - 1);

    if (base + EPT <= nnz) {
        // fast path: 4 independent int4 loads issued back-to-back (MLP=4+1)
        int4 c0 = __ldg((const int4*)(bids + base));
        int4 c1 = __ldg((const int4*)(bids + base + 4));
        int4 c2 = __ldg((const int4*)(bids + base + 8));
        int4 c3 = __ldg((const int4*)(bids + base + 12));
        int cs[EPT] = {c0.x, c0.y, c0.z, c0.w,
                       c1.x, c1.y, c1.z, c1.w,
                       c2.x, c2.y, c2.z, c2.w,
                       c3.x, c3.y, c3.z, c3.w};
        #pragma unroll
        for (int k = 0; k < EPT; k++) {
            for (int b = prev + 1; b <= cs[k]; b++) g_starts[b] = base + k;
            prev = cs[k];
        }
        if (base + EPT == nnz) {
            // owner of the array end fills the sentinel range up to 'batch'
            for (int b = prev + 1; b <= batch; b++) g_starts[b] = nnz;
        }
    } else {
        // scalar tail
        for (int k = 0; k < EPT; k++) {
            int p = base + k;
            if (p >= nnz) { for (int b = prev + 1; b <= batch; b++) g_starts[b] = nnz; break; }
            int cur = __ldg(bids + p);
            for (int b = prev + 1; b <= cur; b++) g_starts[b] = p;
            prev = cur;
        }
    }
}

__global__ __launch_bounds__(BLOCK, 8)
void fm_main(const float* __restrict__ emb,
             const float* __restrict__ vals,
             const int*   __restrict__ fids,
             float*       __restrict__ out)
{
    const int b = blockIdx.x;
    const int t = threadIdx.x & 31;     // float2 lane: dims [2t, 2t+1]
    const int g = threadIdx.x >> 5;     // warp/group 0..7

    const int lo = g_starts[b];
    const int hi = g_starts[b + 1];

    const float2* __restrict__ emb2 = (const float2*)emb;

    float sx = 0.f, sy = 0.f, qx = 0.f, qy = 0.f;

    int i = lo + g;
    // 4-deep gather pipeline per thread
    for (; i + 3 * GROUPS < hi; i += 4 * GROUPS) {
        int f0 = __ldg(fids + i);
        int f1 = __ldg(fids + i +     GROUPS);
        int f2 = __ldg(fids + i + 2 * GROUPS);
        int f3 = __ldg(fids + i + 3 * GROUPS);
        float v0 = __ldg(vals + i);
        float v1 = __ldg(vals + i +     GROUPS);
        float v2 = __ldg(vals + i + 2 * GROUPS);
        float v3 = __ldg(vals + i + 3 * GROUPS);
        float2 e0 = __ldg(emb2 + f0 * 32 + t);
        float2 e1 = __ldg(emb2 + f1 * 32 + t);
        float2 e2 = __ldg(emb2 + f2 * 32 + t);
        float2 e3 = __ldg(emb2 + f3 * 32 + t);

        float ax, ay;
        ax = v0 * e0.x; ay = v0 * e0.y; sx += ax; qx = fmaf(ax, ax, qx); sy += ay; qy = fmaf(ay, ay, qy);
        ax = v1 * e1.x; ay = v1 * e1.y; sx += ax; qx = fmaf(ax, ax, qx); sy += ay; qy = fmaf(ay, ay, qy);
        ax = v2 * e2.x; ay = v2 * e2.y; sx += ax; qx = fmaf(ax, ax, qx); sy += ay; qy = fmaf(ay, ay, qy);
        ax = v3 * e3.x; ay = v3 * e3.y; sx += ax; qx = fmaf(ax, ax, qx); sy += ay; qy = fmaf(ay, ay, qy);
    }
    for (; i < hi; i += GROUPS) {
        int   f = __ldg(fids + i);
        float v = __ldg(vals + i);
        float2 e = __ldg(emb2 + f * 32 + t);
        float ax = v * e.x, ay = v * e.y;
        sx += ax; qx = fmaf(ax, ax, qx);
        sy += ay; qy = fmaf(ay, ay, qy);
    }

    // combine 8 groups through shared memory
    __shared__ float ssx[GROUPS][32], ssy[GROUPS][32];
    __shared__ float sqx[GROUPS][32], sqy[GROUPS][32];
    ssx[g][t] = sx; ssy[g][t] = sy;
    sqx[g][t] = qx; sqy[g][t] = qy;
    __syncthreads();

    if (g == 0) {
        float Sx = sx, Sy = sy, Qx = qx, Qy = qy;
        #pragma unroll
        for (int k = 1; k < GROUPS; k++) {
            Sx += ssx[k][t]; Sy += ssy[k][t];
            Qx += sqx[k][t]; Qy += sqy[k][t];
        }
        float2 o;
        o.x = 0.5f * (Sx * Sx - Qx);
        o.y = 0.5f * (Sy * Sy - Qy);
        ((float2*)out)[b * 32 + t] = o;
    }
}

extern "C" void kernel_launch(void* const* d_in, const int* in_sizes, int n_in,
                              void* d_out, int out_size)
{
    const float* emb  = (const float*)d_in[0];
    const float* vals = (const float*)d_in[1];
    const int*   bids = (const int*)d_in[2];
    const int*   fids = (const int*)d_in[3];
    float* out = (float*)d_out;

    int nnz   = in_sizes[1];
    int batch = out_size / EMBED;   // 4096

    int bthreads = (nnz + EPT - 1) / EPT;
    boundary_kernel<<<(bthreads + 255) / 256, 256>>>(bids, nnz, batch);
    fm_main<<<batch, BLOCK>>>(emb, vals, fids, out);
}